// round 17
// baseline (speedup 1.0000x reference)
#include <cuda_runtime.h>
#include <cuda_bf16.h>
#include <cstdint>

#define NN   1024
#define C    512
#define EB   16384
#define BATCH 8
#define NLOC 128
#define HM   128
#define NSTEPS 10
#define SB   (BATCH*NLOC*NLOC)   /* 131072 */
#define RNG_N (NN*C)             /* 524288 */

// packed-weight word offsets ([K/2][N] uint32 words)
#define WO_EL1 0
#define WO_EL2 131072
#define WO_ERW 262144
#define WO_EFW 393216
#define WO_CL1 655360
#define WO_CL2 786432
#define WO_CRW 917504
#define WO_WA  1048576            /* combined c_fw@m_w1: K=1024,N=128 -> 65536 words */
#define WTOTW  1114112

// ---------------- scratch (no allocation allowed) ----------------
__device__ float g_T[6*NN*C];
__device__ float g_Hs[NN*C], g_Ht[NN*C], g_Rs[NN*C];
__device__ float g_Shat[SB], g_S[SB], g_BmT[SB];
__device__ float g_Am[NN*HM];
__device__ float g_Wa[NN*HM];           // c_fw@m_w1 fp32 (1024x128)
__device__ float g_biasA[2*HM];         // [0:128) s-side (+m_b1), [128:256) t-side
__device__ float g_hbuf[2*NN*C];        // post-relu pre-LN h
__device__ float g_part[2*NN*16*2];     // per-chunk (sum, sumsq)
__device__ int g_cnt[4*NN], g_off[4*(NN+1)], g_cur[4*NN], g_lst[4*EB];
// packed split weights (bf16x2 words)
__device__ unsigned g_Wh[WTOTW], g_Wl[WTOTW];
// split activations (bf16 hi/lo, natural [row][512] layout)
__device__ __nv_bfloat16 g_xh[2*NN*C], g_xl[2*NN*C];
__device__ __nv_bfloat16 g_Rsh[NN*C], g_Rsl[NN*C], g_Rth[NN*C], g_Rtl[NN*C];
__device__ __nv_bfloat16 g_Hlnh[2*NN*C], g_Hlnl[2*NN*C];

// ---------------- threefry-2x32 (matches JAX) ----------------
__host__ __device__ inline void tf2x32(unsigned k0, unsigned k1,
                                       unsigned x0, unsigned x1,
                                       unsigned &o0, unsigned &o1) {
  unsigned ks2 = k0 ^ k1 ^ 0x1BD11BDAu;
  x0 += k0; x1 += k1;
#define TF_ROT(x,r) (((x)<<(r))|((x)>>(32-(r))))
#define TF_RND(r) { x0 += x1; x1 = TF_ROT(x1,(r)); x1 ^= x0; }
  TF_RND(13) TF_RND(15) TF_RND(26) TF_RND(6)
  x0 += k1;  x1 += ks2 + 1u;
  TF_RND(17) TF_RND(29) TF_RND(16) TF_RND(24)
  x0 += ks2; x1 += k0 + 2u;
  TF_RND(13) TF_RND(15) TF_RND(26) TF_RND(6)
  x0 += k0;  x1 += k1 + 3u;
  TF_RND(17) TF_RND(29) TF_RND(16) TF_RND(24)
  x0 += k1;  x1 += ks2 + 4u;
  TF_RND(13) TF_RND(15) TF_RND(26) TF_RND(6)
  x0 += ks2; x1 += k0 + 5u;
  o0 = x0; o1 = x1;
#undef TF_RND
#undef TF_ROT
}

__device__ __forceinline__ void bfsplit(float v, __nv_bfloat16& h, __nv_bfloat16& l) {
  h = __float2bfloat16(v);
  l = __float2bfloat16(v - __bfloat162float(h));
}

// XLA's Giles erfinv + JAX uniform->normal mapping
__device__ __forceinline__ float bits_to_normal(unsigned bits) {
  float f = __uint_as_float((bits >> 9) | 0x3f800000u) - 1.0f;   // [0,1)
  const float LO = -0.99999994f;
  float u = fmaxf(LO, f * 2.0f + LO);
  float w = -log1pf(-u * u);
  float p;
  if (w < 5.0f) {
    w -= 2.5f;
    p = 2.81022636e-08f;
    p = fmaf(p, w, 3.43273939e-07f);
    p = fmaf(p, w, -3.5233877e-06f);
    p = fmaf(p, w, -4.39150654e-06f);
    p = fmaf(p, w, 0.00021858087f);
    p = fmaf(p, w, -0.00125372503f);
    p = fmaf(p, w, -0.00417768164f);
    p = fmaf(p, w, 0.246640727f);
    p = fmaf(p, w, 1.50140941f);
  } else {
    w = sqrtf(w) - 3.0f;
    p = -0.000200214257f;
    p = fmaf(p, w, 0.000100950558f);
    p = fmaf(p, w, 0.00134934322f);
    p = fmaf(p, w, -0.00367342844f);
    p = fmaf(p, w, 0.00573950773f);
    p = fmaf(p, w, -0.0076224613f);
    p = fmaf(p, w, 0.00943887047f);
    p = fmaf(p, w, 1.00167406f);
    p = fmaf(p, w, 2.83297682f);
  }
  return 1.41421356237309504880f * (p * u);
}

// JAX threefry_partitionable: counter (0, i); bits = out0 ^ out1. raw + bf16 split.
__global__ void rng_kernel(unsigned k0, unsigned k1, float* __restrict__ out,
                           __nv_bfloat16* __restrict__ oh, __nv_bfloat16* __restrict__ ol) {
  unsigned i = blockIdx.x * 256u + threadIdx.x;
  unsigned o0, o1;
  tf2x32(k0, k1, 0u, i, o0, o1);
  float v = bits_to_normal(o0 ^ o1);
  out[i] = v;
  __nv_bfloat16 h, l;
  bfsplit(v, h, l);
  oh[i] = h; ol[i] = l;
}

// fp32 -> bf16 hi/lo splitter (activations)
__global__ void split_a(const float* __restrict__ in, __nv_bfloat16* __restrict__ hi,
                        __nv_bfloat16* __restrict__ lo, int n) {
  int i = blockIdx.x * 256 + threadIdx.x;
  if (i >= n) return;
  __nv_bfloat16 h, l;
  bfsplit(in[i], h, l);
  hi[i] = h; lo[i] = l;
}

// weight split+pack: W[K][N] fp32 -> Wh/Wl[K/2][N] bf16x2 words (k pair in one word)
__global__ void split_pack_w(const float* __restrict__ W, unsigned* __restrict__ Wh,
                             unsigned* __restrict__ Wl, int Khalf, int N) {
  int i = blockIdx.x * 256 + threadIdx.x;
  if (i >= Khalf * N) return;
  int j = i / N, n = i % N;
  float v0 = W[(size_t)(2 * j) * N + n];
  float v1 = W[(size_t)(2 * j + 1) * N + n];
  __nv_bfloat16 h0, l0, h1, l1;
  bfsplit(v0, h0, l0);
  bfsplit(v1, h1, l1);
  __nv_bfloat162 ph = __halves2bfloat162(h0, h1);   // low = k even
  __nv_bfloat162 pl = __halves2bfloat162(l0, l1);
  Wh[i] = *reinterpret_cast<unsigned*>(&ph);
  Wl[i] = *reinterpret_cast<unsigned*>(&pl);
}

// combined weight: Wa = c_fw @ m_w1 (fp32), biasA = {c_fb@m_w1 + m_b1, c_fb@m_w1}
__global__ void combine_w(const float* __restrict__ cfw, const float* __restrict__ mw1,
                          const float* __restrict__ cfb, const float* __restrict__ mb1,
                          float* __restrict__ Wa, float* __restrict__ biasA) {
  int k = blockIdx.x, h = threadIdx.x;   // grid 1025, block 128
  if (k < NN) {
    float acc = 0.f;
    for (int j = 0; j < C; j++)
      acc = fmaf(cfw[(size_t)k * C + j], mw1[(size_t)j * HM + h], acc);
    Wa[(size_t)k * HM + h] = acc;
  } else {
    float acc = 0.f;
    for (int j = 0; j < C; j++)
      acc = fmaf(cfb[j], mw1[(size_t)j * HM + h], acc);
    biasA[h] = acc + mb1[h];
    biasA[HM + h] = acc;
  }
}

// ---------------- CSR build ----------------
__global__ void csr_count(const int* __restrict__ eis, const int* __restrict__ eit,
                          int* __restrict__ cnt) {
  int e = blockIdx.x * 256 + threadIdx.x;
  if (e >= EB) return;
  int ss = eis[e], sd = eis[EB + e];
  atomicAdd(&cnt[0 * NN + sd], 1);
  atomicAdd(&cnt[1 * NN + ss], 1);
  int ts = eit[e], td = eit[EB + e];
  atomicAdd(&cnt[2 * NN + td], 1);
  atomicAdd(&cnt[3 * NN + ts], 1);
}

__global__ void csr_scan(const int* __restrict__ cnt, int* __restrict__ off,
                         int* __restrict__ cur) {
  int a = blockIdx.x, t = threadIdx.x;
  __shared__ int sm[NN];
  int v = cnt[a * NN + t];
  sm[t] = v; __syncthreads();
  for (int o = 1; o < NN; o <<= 1) {
    int u = (t >= o) ? sm[t - o] : 0;
    __syncthreads();
    sm[t] += u;
    __syncthreads();
  }
  int excl = sm[t] - v;
  off[a * (NN + 1) + t] = excl;
  cur[a * NN + t] = excl;
  if (t == NN - 1) off[a * (NN + 1) + NN] = sm[t];
}

__global__ void csr_fill(const int* __restrict__ eis, const int* __restrict__ eit,
                         int* __restrict__ cur, int* __restrict__ lst) {
  int e = blockIdx.x * 256 + threadIdx.x;
  if (e >= EB) return;
  int ss = eis[e], sd = eis[EB + e];
  int p = atomicAdd(&cur[0 * NN + sd], 1); lst[0 * EB + p] = ss;
  p = atomicAdd(&cur[1 * NN + ss], 1);     lst[1 * EB + p] = sd;
  int ts = eit[e], td = eit[EB + e];
  p = atomicAdd(&cur[2 * NN + td], 1);     lst[2 * EB + p] = ts;
  p = atomicAdd(&cur[3 * NN + ts], 1);     lst[3 * EB + p] = td;
}

// ---------------- bf16x3 tensor-core GEMM (ldmatrix + 3-stage cp.async) ----------------
struct P6 {
  const __nv_bfloat16* Ahi[6];   // k<512 half, row stride 512
  const __nv_bfloat16* Alo[6];
  const __nv_bfloat16* Ahi2[6];  // k>=512 (virtual concat)
  const __nv_bfloat16* Alo2[6];
  const unsigned* Bh[6];         // packed [K/2][N] words
  const unsigned* Bl[6];
  float*          Craw[6];       // nullable
  __nv_bfloat16*  Chi[6];        // nullable split epilogue
  __nv_bfloat16*  Clo[6];
  const float*    bias[6];
  int trT[6];                    // store Craw transposed [b][h][j] (Nn must be 128)
};

__device__ __forceinline__ void mma16(float* d, const unsigned* a, const unsigned* b) {
  asm volatile(
    "mma.sync.aligned.m16n8k16.row.col.f32.bf16.bf16.f32 "
    "{%0,%1,%2,%3}, {%4,%5,%6,%7}, {%8,%9}, {%0,%1,%2,%3};\n"
    : "+f"(d[0]), "+f"(d[1]), "+f"(d[2]), "+f"(d[3])
    : "r"(a[0]), "r"(a[1]), "r"(a[2]), "r"(a[3]), "r"(b[0]), "r"(b[1]));
}

__device__ __forceinline__ void ldsm4(unsigned* r, unsigned addr) {
  asm volatile("ldmatrix.sync.aligned.m8n8.x4.shared.b16 {%0,%1,%2,%3}, [%4];"
    : "=r"(r[0]), "=r"(r[1]), "=r"(r[2]), "=r"(r[3]) : "r"(addr));
}

__device__ __forceinline__ void cpa16(unsigned dst, const void* src) {
  asm volatile("cp.async.cg.shared.global [%0], [%1], 16;" :: "r"(dst), "l"(src));
}
__device__ __forceinline__ void cp_commit() { asm volatile("cp.async.commit_group;"); }

// 3-stage smem: A[3buf][2hl][BM][12w] + B[3buf][2hl][8][BN+8]
template<int BM, int BN>
constexpr int smem_b() { return (3 * 2 * BM * 12 + 3 * 2 * 8 * (BN + 8)) * 4; }

// BK=16. A fragments via ldmatrix.x4 from [m][kpair] rows (pitch 12 words);
// B fragments scalar LDS from [kpair][n] rows (pitch BN+8).
template<int BM, int BN>
__global__ __launch_bounds__(256) void gemm_bf16(P6 p, int Nn, int K) {
  constexpr int AP = 12, BP = BN + 8;
  constexpr int NAOP = 2 * BM * 2;          // 16B ops per A tile
  constexpr int NBOP = 2 * 8 * (BN / 4);    // 16B ops per B tile
  constexpr int WM = BM / 2, WN = BN / 4;
  constexpr int MI = WM / 16, NI = WN / 8;

  const int tid = threadIdx.x;
  const int z = blockIdx.z;
  const __nv_bfloat16* __restrict__ Ahi = p.Ahi[z];
  const __nv_bfloat16* __restrict__ Alo = p.Alo[z];
  const __nv_bfloat16* __restrict__ Ahi2 = p.Ahi2[z];
  const __nv_bfloat16* __restrict__ Alo2 = p.Alo2[z];
  const unsigned* __restrict__ Bh = p.Bh[z];
  const unsigned* __restrict__ Bl = p.Bl[z];
  float* __restrict__ Craw = p.Craw[z];
  __nv_bfloat16* __restrict__ Chi = p.Chi[z];
  __nv_bfloat16* __restrict__ Clo = p.Clo[z];
  const float* __restrict__ bias = p.bias[z];
  const int trT = p.trT[z];
  const int row0 = blockIdx.y * BM, col0 = blockIdx.x * BN;

  extern __shared__ unsigned smem_u[];
  unsigned* As = smem_u;
  unsigned* Bs = smem_u + 3 * 2 * BM * AP;
  const unsigned as_u = (unsigned)__cvta_generic_to_shared(As);
  const unsigned bs_u = (unsigned)__cvta_generic_to_shared(Bs);

  const int lane = tid & 31;
  const int wid = tid >> 5;
  const int gid = lane >> 2, tg = lane & 3;
  const int wr = wid >> 2, wc = wid & 3;   // 2 x 4 warps

  float acc[MI][NI][4];
#pragma unroll
  for (int i = 0; i < MI; i++)
#pragma unroll
    for (int j = 0; j < NI; j++)
#pragma unroll
      for (int q = 0; q < 4; q++) acc[i][j][q] = 0.f;

  const int nk = K >> 4;

  auto ldg = [&](int kt, int buf) {
    const __nv_bfloat16* Ah = (kt >= 512) ? Ahi2 : Ahi;
    const __nv_bfloat16* Al = (kt >= 512) ? Alo2 : Alo;
    int ko = kt & 511;
    int ktp = kt >> 1;
#pragma unroll
    for (int i = 0; i < (NAOP + 255) / 256; i++) {
      int idx = tid + i * 256;
      if (NAOP < 256 || NAOP % 256) { if (idx >= NAOP) break; }
      int hl = idx / (BM * 2);
      int rem = idx - hl * (BM * 2);
      int m = rem >> 1, ch = rem & 1;
      const __nv_bfloat16* src = (hl ? Al : Ah) + (size_t)(row0 + m) * 512 + ko + ch * 8;
      unsigned dst = as_u + (unsigned)((((buf * 2 + hl) * BM + m) * AP + ch * 4) * 4);
      cpa16(dst, src);
    }
#pragma unroll
    for (int i = 0; i < (NBOP + 255) / 256; i++) {
      int idx = tid + i * 256;
      if (NBOP < 256 || NBOP % 256) { if (idx >= NBOP) break; }
      int hl = idx / (8 * (BN / 4));
      int rem = idx - hl * (8 * (BN / 4));
      int kp = rem / (BN / 4), n4 = rem % (BN / 4);
      const unsigned* src = (hl ? Bl : Bh) + (size_t)(ktp + kp) * Nn + col0 + n4 * 4;
      unsigned dst = bs_u + (unsigned)((((buf * 2 + hl) * 8 + kp) * BP + n4 * 4) * 4);
      cpa16(dst, src);
    }
  };

  const int lrow = lane & 15;
  const int lko = (lane & 16) ? 4 : 0;

  auto compute = [&](int buf) {
    const unsigned* B0 = Bs + (size_t)((buf * 2 + 0) * 8) * BP;
    const unsigned* B1 = Bs + (size_t)((buf * 2 + 1) * 8) * BP;
    unsigned ah[MI][4], al[MI][4], bh[NI][2], bl[NI][2];
#pragma unroll
    for (int mi = 0; mi < MI; mi++) {
      int m = wr * WM + mi * 16 + lrow;
      ldsm4(ah[mi], as_u + (unsigned)((((buf * 2 + 0) * BM + m) * AP + lko) * 4));
      ldsm4(al[mi], as_u + (unsigned)((((buf * 2 + 1) * BM + m) * AP + lko) * 4));
    }
#pragma unroll
    for (int ni = 0; ni < NI; ni++) {
      int n = wc * WN + ni * 8 + gid;
      bh[ni][0] = B0[tg * BP + n];
      bh[ni][1] = B0[(tg + 4) * BP + n];
      bl[ni][0] = B1[tg * BP + n];
      bl[ni][1] = B1[(tg + 4) * BP + n];
    }
#pragma unroll
    for (int mi = 0; mi < MI; mi++)
#pragma unroll
      for (int ni = 0; ni < NI; ni++) {
        mma16(acc[mi][ni], ah[mi], bl[ni]);
        mma16(acc[mi][ni], al[mi], bh[ni]);
        mma16(acc[mi][ni], ah[mi], bh[ni]);
      }
  };

  ldg(0, 0);
  cp_commit();
  if (nk > 1) { ldg(16, 1); cp_commit(); }
  for (int t = 0; t < nk; t++) {
    int buf = t % 3;
    if (t + 1 < nk) {
      asm volatile("cp.async.wait_group 1;");
    } else {
      asm volatile("cp.async.wait_group 0;");
    }
    __syncthreads();
    if (t + 2 < nk) {
      ldg((t + 2) << 4, (t + 2) % 3);
      cp_commit();
    }
    compute(buf);
  }

#pragma unroll
  for (int mi = 0; mi < MI; mi++) {
#pragma unroll
    for (int ni = 0; ni < NI; ni++) {
      int r = row0 + wr * WM + mi * 16 + gid;
      int c = col0 + wc * WN + ni * 8 + tg * 2;
      float b0 = bias ? bias[c] : 0.f;
      float b1 = bias ? bias[c + 1] : 0.f;
      float v[4] = {acc[mi][ni][0] + b0, acc[mi][ni][1] + b1,
                    acc[mi][ni][2] + b0, acc[mi][ni][3] + b1};
      if (Craw) {
        if (trT) {
          int b_ = r >> 7, j_ = r & 127;
          int b2_ = (r + 8) >> 7, j2_ = (r + 8) & 127;
          Craw[(size_t)b_ * 16384 + (c) * 128 + j_]       = v[0];
          Craw[(size_t)b_ * 16384 + (c + 1) * 128 + j_]   = v[1];
          Craw[(size_t)b2_ * 16384 + (c) * 128 + j2_]     = v[2];
          Craw[(size_t)b2_ * 16384 + (c + 1) * 128 + j2_] = v[3];
        } else {
          size_t i0 = (size_t)r * Nn + c, i1 = (size_t)(r + 8) * Nn + c;
          Craw[i0] = v[0]; Craw[i0 + 1] = v[1];
          Craw[i1] = v[2]; Craw[i1 + 1] = v[3];
        }
      }
      if (Chi) {
        size_t i0 = (size_t)r * Nn + c, i1 = (size_t)(r + 8) * Nn + c;
        __nv_bfloat16 h, l;
        bfsplit(v[0], h, l); Chi[i0] = h;     Clo[i0] = l;
        bfsplit(v[1], h, l); Chi[i0 + 1] = h; Clo[i0 + 1] = l;
        bfsplit(v[2], h, l); Chi[i1] = h;     Clo[i1] = l;
        bfsplit(v[3], h, l); Chi[i1 + 1] = h; Clo[i1 + 1] = l;
      }
    }
  }
}

// ---------------- smem-staged chunked edge-mean (+ReLU) + LN partials ----------------
// grid: (BATCH, C/32, 2 sides), block 256. Writes post-ReLU h + per-chunk (sum, sumsq).
__global__ __launch_bounds__(256)
void agg_chunk(const float* __restrict__ T, const int* __restrict__ off,
               const int* __restrict__ lst, float* __restrict__ Hbuf,
               float* __restrict__ part) {
  const int b = blockIdx.x, chk = blockIdx.y, side = blockIdx.z;
  const float* T1 = T + (size_t)(side * 3 + 0) * NN * C;
  const float* T2 = T + (size_t)(side * 3 + 1) * NN * C;
  const float* TR = T + (size_t)(side * 3 + 2) * NN * C;
  const int* inoff = off + (side * 2 + 0) * (NN + 1);
  const int* outoff = off + (side * 2 + 1) * (NN + 1);
  const int* inlst = lst + (size_t)(side * 2 + 0) * EB;
  const int* outlst = lst + (size_t)(side * 2 + 1) * EB;
  const int c0 = chk * 32;
  __shared__ float s1[128][33], s2[128][33];
  const int tid = threadIdx.x;
  for (int i = tid; i < 128 * 32; i += 256) {
    int r = i >> 5, c = i & 31;
    s1[r][c] = T1[(size_t)(b * 128 + r) * C + c0 + c];
    s2[r][c] = T2[(size_t)(b * 128 + r) * C + c0 + c];
  }
  __syncthreads();
  const int ln = tid >> 1;           // local node 0..127
  const int half = tid & 1;          // col half (16 cols each)
  const int n = b * 128 + ln;
  const int cb = half * 16;
  int is = inoff[n], ie = inoff[n + 1];
  int os = outoff[n], oe = outoff[n + 1];
  float inv1 = 1.f / (float)max(ie - is, 1);
  float inv2 = 1.f / (float)max(oe - os, 1);
  float a1[16], a2[16];
#pragma unroll
  for (int c = 0; c < 16; c++) { a1[c] = 0.f; a2[c] = 0.f; }
  for (int e = is; e < ie; e++) {
    int m = inlst[e] & 127;
#pragma unroll
    for (int c = 0; c < 16; c++) a1[c] += s1[m][cb + c];
  }
  for (int e = os; e < oe; e++) {
    int m = outlst[e] & 127;
#pragma unroll
    for (int c = 0; c < 16; c++) a2[c] += s2[m][cb + c];
  }
  float psum = 0.f, psq = 0.f;
  size_t base = (size_t)(side * NN + n) * C + c0 + cb;
#pragma unroll
  for (int c = 0; c < 16; c++) {
    float v = TR[(size_t)n * C + c0 + cb + c] + a1[c] * inv1 + a2[c] * inv2;
    v = fmaxf(v, 0.f);
    Hbuf[base + c] = v;
    psum += v;
    psq = fmaf(v, v, psq);
  }
  psum += __shfl_xor_sync(0xffffffffu, psum, 1);
  psq  += __shfl_xor_sync(0xffffffffu, psq, 1);
  if (half == 0) {
    size_t pi = (((size_t)side * NN + n) * 16 + chk) * 2;
    part[pi] = psum;
    part[pi + 1] = psq;
  }
}

// LN apply from partials: grid (NN, 2), block 256. bf16-split out.
__global__ __launch_bounds__(256)
void ln_apply(const float* __restrict__ Hbuf, const float* __restrict__ part,
              const float* __restrict__ gamma, const float* __restrict__ beta,
              __nv_bfloat16* __restrict__ Hhi, __nv_bfloat16* __restrict__ Hlo) {
  int n = blockIdx.x, side = blockIdx.y, t = threadIdx.x;
  float su = 0.f, sq = 0.f;
  size_t pb = (((size_t)side * NN + n) * 16) * 2;
#pragma unroll
  for (int ch = 0; ch < 16; ch++) {
    su += part[pb + ch * 2];
    sq += part[pb + ch * 2 + 1];
  }
  float mu = su * (1.0f / C);
  float var = sq * (1.0f / C) - mu * mu;
  float rstd = rsqrtf(var + 1e-5f);
  size_t base = (size_t)(side * NN + n) * C;
  int c0 = t, c1 = t + 256;
  float v0 = (Hbuf[base + c0] - mu) * rstd * gamma[c0] + beta[c0];
  float v1 = (Hbuf[base + c1] - mu) * rstd * gamma[c1] + beta[c1];
  __nv_bfloat16 h, l;
  bfsplit(v0, h, l); Hhi[base + c0] = h; Hlo[base + c0] = l;
  bfsplit(v1, h, l); Hhi[base + c1] = h; Hlo[base + c1] = l;
}

// ---------------- S_hat = Hs_b @ Ht_b^T ----------------
__global__ __launch_bounds__(256)
void shat_kernel(const float* __restrict__ Hs, const float* __restrict__ Ht,
                 float* __restrict__ Shat) {
  int b = blockIdx.z, s0 = blockIdx.y * 32, t0 = blockIdx.x * 32;
  int tid = threadIdx.x, tx = tid & 15, ty = tid >> 4;
  __shared__ float sA[32][33], sBt[32][33];
  float acc[2][2] = {};
  for (int k0 = 0; k0 < C; k0 += 32) {
#pragma unroll
    for (int l = 0; l < 4; l++) {
      int idx = tid + l * 256;
      int r = idx >> 5, k = idx & 31;
      sA[r][k] = Hs[(b * NLOC + s0 + r) * C + k0 + k];
      sBt[r][k] = Ht[(b * NLOC + t0 + r) * C + k0 + k];
    }
    __syncthreads();
#pragma unroll
    for (int k = 0; k < 32; k++) {
      float a0 = sA[ty * 2][k], a1 = sA[ty * 2 + 1][k];
      float b0 = sBt[tx * 2][k], b1 = sBt[tx * 2 + 1][k];
      acc[0][0] = fmaf(a0, b0, acc[0][0]);
      acc[0][1] = fmaf(a0, b1, acc[0][1]);
      acc[1][0] = fmaf(a1, b0, acc[1][0]);
      acc[1][1] = fmaf(a1, b1, acc[1][1]);
    }
    __syncthreads();
  }
#pragma unroll
  for (int i = 0; i < 2; i++)
#pragma unroll
    for (int j = 0; j < 2; j++)
      Shat[b * (NLOC * NLOC) + (s0 + ty * 2 + i) * NLOC + (t0 + tx * 2 + j)] = acc[i][j];
}

// ---------------- row softmax, dual output ----------------
__global__ void softmax2(const float* __restrict__ in, float* __restrict__ o1,
                         float* __restrict__ o2) {
  int row = blockIdx.x, t = threadIdx.x;
  __shared__ float red[128];
  float v = in[row * 128 + t];
  red[t] = v; __syncthreads();
  for (int o = 64; o > 0; o >>= 1) { if (t < o) red[t] = fmaxf(red[t], red[t + o]); __syncthreads(); }
  float mx = red[0]; __syncthreads();
  float e = expf(v - mx);
  red[t] = e; __syncthreads();
  for (int o = 64; o > 0; o >>= 1) { if (t < o) red[t] += red[t + o]; __syncthreads(); }
  float r = e / red[0];
  o1[row * 128 + t] = r;
  o2[row * 128 + t] = r;
}

// ---------------- R_t = S^T @ R_s, bf16-split output ----------------
__global__ __launch_bounds__(256)
void rt_kernel(const float* __restrict__ S, const float* __restrict__ Rs,
               __nv_bfloat16* __restrict__ Rthi, __nv_bfloat16* __restrict__ Rtlo) {
  int b = blockIdx.y, t0 = blockIdx.x * 16;
  int tid = threadIdx.x;
  __shared__ float sS[128][16];
#pragma unroll
  for (int l = 0; l < 8; l++) {
    int idx = tid + l * 256;
    int s = idx >> 4, tt = idx & 15;
    sS[s][tt] = S[b * (NLOC * NLOC) + s * NLOC + t0 + tt];
  }
  __syncthreads();
  int c = tid;
  float acc0[16] = {}, acc1[16] = {};
  for (int s = 0; s < NLOC; s++) {
    float r0 = Rs[(b * NLOC + s) * C + c];
    float r1 = Rs[(b * NLOC + s) * C + c + 256];
#pragma unroll
    for (int tt = 0; tt < 16; tt++) {
      float sv = sS[s][tt];
      acc0[tt] = fmaf(sv, r0, acc0[tt]);
      acc1[tt] = fmaf(sv, r1, acc1[tt]);
    }
  }
#pragma unroll
  for (int tt = 0; tt < 16; tt++) {
    size_t i0 = (size_t)(b * NLOC + t0 + tt) * C + c;
    __nv_bfloat16 h, l;
    bfsplit(acc0[tt], h, l); Rthi[i0] = h;       Rtlo[i0] = l;
    bfsplit(acc1[tt], h, l); Rthi[i0 + 256] = h; Rtlo[i0 + 256] = l;
  }
}

// ---------------- fused: S_hat += MLP pairwise; S_next = softmax(row) ----------------
__global__ void pairwise_sm(const float* __restrict__ A, const float* __restrict__ BmT,
                            const float* __restrict__ w2, const float* __restrict__ b2,
                            float* __restrict__ Shat, float* __restrict__ Sout) {
  int bi = blockIdx.x;
  int b = bi >> 7, j = threadIdx.x;
  __shared__ float sA[128], sw[128], red[128];
  sA[j] = A[bi * HM + j];
  sw[j] = w2[j];
  __syncthreads();
  float acc = 0.f;
  const float* Bp = BmT + b * (HM * NLOC) + j;
#pragma unroll 8
  for (int h = 0; h < HM; h++) {
    float d = sA[h] - Bp[h * NLOC];
    acc = fmaf(fmaxf(d, 0.f), sw[h], acc);
  }
  float val = Shat[bi * NLOC + j] + acc + b2[0];
  Shat[bi * NLOC + j] = val;
  red[j] = val; __syncthreads();
  for (int o = 64; o > 0; o >>= 1) { if (j < o) red[j] = fmaxf(red[j], red[j + o]); __syncthreads(); }
  float mx = red[0]; __syncthreads();
  float e = expf(val - mx);
  red[j] = e; __syncthreads();
  for (int o = 64; o > 0; o >>= 1) { if (j < o) red[j] += red[j + o]; __syncthreads(); }
  Sout[bi * NLOC + j] = e / red[0];
}

// ---------------- host side ----------------
struct Ptrs {
  float *T, *Hs, *Ht, *Rs, *Shat, *S, *BmT, *Am, *Wa, *biasA, *hbuf, *part;
  unsigned *Wh, *Wl;
  __nv_bfloat16 *xh, *xl, *Rsh, *Rsl, *Rth, *Rtl, *Hlnh, *Hlnl;
  int *cnt, *off, *cur, *lst;
};

extern "C" void kernel_launch(void* const* d_in, const int* in_sizes, int n_in,
                              void* d_out, int out_size) {
  const float* x_s  = (const float*)d_in[0];
  const int*   ei_s = (const int*)d_in[1];
  const float* x_t  = (const float*)d_in[4];
  const int*   ei_t = (const int*)d_in[5];
  const float* e_lin1 = (const float*)d_in[8];
  const float* e_lin2 = (const float*)d_in[9];
  const float* e_rw   = (const float*)d_in[10];
  const float* e_rb   = (const float*)d_in[11];
  const float* e_g    = (const float*)d_in[12];
  const float* e_b    = (const float*)d_in[13];
  const float* e_fw   = (const float*)d_in[14];
  const float* e_fb   = (const float*)d_in[15];
  const float* c_lin1 = (const float*)d_in[16];
  const float* c_lin2 = (const float*)d_in[17];
  const float* c_rw   = (const float*)d_in[18];
  const float* c_rb   = (const float*)d_in[19];
  const float* c_g    = (const float*)d_in[20];
  const float* c_b    = (const float*)d_in[21];
  const float* c_fw   = (const float*)d_in[22];
  const float* c_fb   = (const float*)d_in[23];
  const float* m_w1   = (const float*)d_in[24];
  const float* m_b1   = (const float*)d_in[25];
  const float* m_w2   = (const float*)d_in[26];
  const float* m_b2   = (const float*)d_in[27];
  float* out = (float*)d_out;

  Ptrs q;
  cudaGetSymbolAddress((void**)&q.T,    g_T);
  cudaGetSymbolAddress((void**)&q.Hs,   g_Hs);
  cudaGetSymbolAddress((void**)&q.Ht,   g_Ht);
  cudaGetSymbolAddress((void**)&q.Rs,   g_Rs);
  cudaGetSymbolAddress((void**)&q.Shat, g_Shat);
  cudaGetSymbolAddress((void**)&q.S,    g_S);
  cudaGetSymbolAddress((void**)&q.BmT,  g_BmT);
  cudaGetSymbolAddress((void**)&q.Am,   g_Am);
  cudaGetSymbolAddress((void**)&q.Wa,   g_Wa);
  cudaGetSymbolAddress((void**)&q.biasA, g_biasA);
  cudaGetSymbolAddress((void**)&q.hbuf, g_hbuf);
  cudaGetSymbolAddress((void**)&q.part, g_part);
  cudaGetSymbolAddress((void**)&q.Wh,   g_Wh);
  cudaGetSymbolAddress((void**)&q.Wl,   g_Wl);
  cudaGetSymbolAddress((void**)&q.xh,   g_xh);
  cudaGetSymbolAddress((void**)&q.xl,   g_xl);
  cudaGetSymbolAddress((void**)&q.Rsh,  g_Rsh);
  cudaGetSymbolAddress((void**)&q.Rsl,  g_Rsl);
  cudaGetSymbolAddress((void**)&q.Rth,  g_Rth);
  cudaGetSymbolAddress((void**)&q.Rtl,  g_Rtl);
  cudaGetSymbolAddress((void**)&q.Hlnh, g_Hlnh);
  cudaGetSymbolAddress((void**)&q.Hlnl, g_Hlnl);
  cudaGetSymbolAddress((void**)&q.cnt,  g_cnt);
  cudaGetSymbolAddress((void**)&q.off,  g_off);
  cudaGetSymbolAddress((void**)&q.cur,  g_cur);
  cudaGetSymbolAddress((void**)&q.lst,  g_lst);

  cudaFuncSetAttribute(gemm_bf16<64, 64>,  cudaFuncAttributeMaxDynamicSharedMemorySize, smem_b<64, 64>());
  cudaFuncSetAttribute(gemm_bf16<64, 128>, cudaFuncAttributeMaxDynamicSharedMemorySize, smem_b<64, 128>());
  cudaFuncSetAttribute(gemm_bf16<32, 64>,  cudaFuncAttributeMaxDynamicSharedMemorySize, smem_b<32, 64>());

  // combined loop weight: Wa = c_fw@m_w1, biasA
  combine_w<<<NN + 1, HM>>>(c_fw, m_w1, c_fb, m_b1, q.Wa, q.biasA);

  // weight split+pack (once per call)
  struct { const float* src; size_t woff; int kh, n; } wj[8] = {
    {e_lin1, WO_EL1, C / 2, C}, {e_lin2, WO_EL2, C / 2, C}, {e_rw, WO_ERW, C / 2, C},
    {e_fw, WO_EFW, C, C},
    {c_lin1, WO_CL1, C / 2, C}, {c_lin2, WO_CL2, C / 2, C}, {c_rw, WO_CRW, C / 2, C},
    {q.Wa, WO_WA, NN / 2, HM},
  };
  for (int i = 0; i < 8; i++) {
    int n = wj[i].kh * wj[i].n;
    split_pack_w<<<(n + 255) / 256, 256>>>(wj[i].src, q.Wh + wj[i].woff,
                                           q.Wl + wj[i].woff, wj[i].kh, wj[i].n);
  }
  split_a<<<NN * C / 256, 256>>>(x_s, q.xh, q.xl, NN * C);
  split_a<<<NN * C / 256, 256>>>(x_t, q.xh + NN * C, q.xl + NN * C, NN * C);

  // CSR build
  cudaMemsetAsync(q.cnt, 0, 4 * NN * sizeof(int));
  csr_count<<<(EB + 255) / 256, 256>>>(ei_s, ei_t, q.cnt);
  csr_scan<<<4, 1024>>>(q.cnt, q.off, q.cur);
  csr_fill<<<(EB + 255) / 256, 256>>>(ei_s, ei_t, q.cur, q.lst);

  // ---- embedding GNN pair ----
  {
    P6 p3 = {};
    for (int z = 0; z < 6; z++) {
      int side = z / 3, w = z % 3;
      p3.Ahi[z] = q.xh + (size_t)side * NN * C;
      p3.Alo[z] = q.xl + (size_t)side * NN * C;
      p3.Ahi2[z] = p3.Ahi[z]; p3.Alo2[z] = p3.Alo[z];
      size_t wo = (w == 0) ? WO_EL1 : (w == 1) ? WO_EL2 : WO_ERW;
      p3.Bh[z] = q.Wh + wo; p3.Bl[z] = q.Wl + wo;
      p3.Craw[z] = q.T + (size_t)z * NN * C;
      p3.bias[z] = (w == 2) ? e_rb : nullptr;
    }
    gemm_bf16<64, 64><<<dim3(C / 64, NN / 64, 6), 256, smem_b<64, 64>()>>>(p3, C, C);
    agg_chunk<<<dim3(BATCH, C / 32, 2), 256>>>(q.T, q.off, q.lst, q.hbuf, q.part);
    ln_apply<<<dim3(NN, 2), 256>>>(q.hbuf, q.part, e_g, e_b, q.Hlnh, q.Hlnl);
    P6 pc = {};
    for (int z = 0; z < 2; z++) {
      pc.Ahi[z] = q.xh + (size_t)z * NN * C;
      pc.Alo[z] = q.xl + (size_t)z * NN * C;
      pc.Ahi2[z] = q.Hlnh + (size_t)z * NN * C;
      pc.Alo2[z] = q.Hlnl + (size_t)z * NN * C;
      pc.Bh[z] = q.Wh + WO_EFW; pc.Bl[z] = q.Wl + WO_EFW;
      pc.Craw[z] = z ? q.Ht : q.Hs;
      pc.bias[z] = e_fb;
    }
    gemm_bf16<64, 128><<<dim3(C / 128, NN / 64, 2), 256, smem_b<64, 128>()>>>(pc, C, 2 * C);
  }

  shat_kernel<<<dim3(4, 4, BATCH), 256>>>(q.Hs, q.Ht, q.Shat);
  softmax2<<<NN, 128>>>(q.Shat, out, q.S);   // S_0 and first-loop S

  for (int t = 0; t < NSTEPS; t++) {
    unsigned fk0, fk1;
    tf2x32(0u, 42u, 0u, (unsigned)t, fk0, fk1);
    rng_kernel<<<RNG_N / 256, 256>>>(fk0, fk1, q.Rs, q.Rsh, q.Rsl);
    rt_kernel<<<dim3(8, BATCH), 256>>>(q.S, q.Rs, q.Rth, q.Rtl);
    // RelConv GEMMs (6z) on (Rs, Rt)
    P6 p3 = {};
    for (int z = 0; z < 6; z++) {
      int side = z / 3, w = z % 3;
      p3.Ahi[z] = side ? q.Rth : q.Rsh;
      p3.Alo[z] = side ? q.Rtl : q.Rsl;
      p3.Ahi2[z] = p3.Ahi[z]; p3.Alo2[z] = p3.Alo[z];
      size_t wo = (w == 0) ? WO_CL1 : (w == 1) ? WO_CL2 : WO_CRW;
      p3.Bh[z] = q.Wh + wo; p3.Bl[z] = q.Wl + wo;
      p3.Craw[z] = q.T + (size_t)z * NN * C;
      p3.bias[z] = (w == 2) ? c_rb : nullptr;
    }
    gemm_bf16<64, 64><<<dim3(C / 64, NN / 64, 6), 256, smem_b<64, 64>()>>>(p3, C, C);
    agg_chunk<<<dim3(BATCH, C / 32, 2), 256>>>(q.T, q.off, q.lst, q.hbuf, q.part);
    ln_apply<<<dim3(NN, 2), 256>>>(q.hbuf, q.part, c_g, c_b, q.Hlnh, q.Hlnl);
    // Fused A-GEMM: Am = [Rs|Hln_s]@Wa + biasA_s ; BmT = ([Rt|Hln_t]@Wa + biasA_t)^T
    P6 pa = {};
    for (int z = 0; z < 2; z++) {
      pa.Ahi[z] = z ? q.Rth : q.Rsh;
      pa.Alo[z] = z ? q.Rtl : q.Rsl;
      pa.Ahi2[z] = q.Hlnh + (size_t)z * NN * C;
      pa.Alo2[z] = q.Hlnl + (size_t)z * NN * C;
      pa.Bh[z] = q.Wh + WO_WA; pa.Bl[z] = q.Wl + WO_WA;
      pa.Craw[z] = z ? q.BmT : q.Am;
      pa.bias[z] = q.biasA + (z ? HM : 0);
      pa.trT[z] = z;
    }
    gemm_bf16<32, 64><<<dim3(HM / 64, NN / 32, 2), 256, smem_b<32, 64>()>>>(pa, HM, 2 * C);
    pairwise_sm<<<NN, 128>>>(q.Am, q.BmT, m_w2, m_b2, q.Shat,
                             (t == NSTEPS - 1) ? (out + SB) : q.S);
  }
}